// round 1
// baseline (speedup 1.0000x reference)
#include <cuda_runtime.h>
#include <cuda_bf16.h>
#include <math.h>

// Problem dims (fixed by the dataset)
#define M_DIM 2048      // batch B
#define K_DIM 512       // input size D
#define N_DIM 16384     // output size (side*side)
#define SIDE  128

// Scratch (no cudaMalloc allowed)
__device__ float g_w2[N_DIM];
__device__ float g_x2[M_DIM];
__device__ int   g_bmu[M_DIM];

// ---------------------------------------------------------------------------
// w2[n] = sum_k W[k][n]^2   (W is [K][N] row-major; coalesced across n)
// ---------------------------------------------------------------------------
__global__ void w2_kernel(const float* __restrict__ W) {
    int n = blockIdx.x * blockDim.x + threadIdx.x;
    if (n < N_DIM) {
        float s = 0.f;
        #pragma unroll 8
        for (int k = 0; k < K_DIM; k++) {
            float v = W[(size_t)k * N_DIM + n];
            s += v * v;
        }
        g_w2[n] = s;
    }
}

// ---------------------------------------------------------------------------
// x2[b] = sum_k X[b][k]^2  (one warp per row, float4 loads)
// ---------------------------------------------------------------------------
__global__ void x2_kernel(const float* __restrict__ X) {
    int gwarp = (blockIdx.x * blockDim.x + threadIdx.x) >> 5;
    int lane  = threadIdx.x & 31;
    if (gwarp < M_DIM) {
        const float4* row = (const float4*)(X + (size_t)gwarp * K_DIM);
        float s = 0.f;
        #pragma unroll
        for (int i = lane; i < K_DIM / 4; i += 32) {
            float4 v = row[i];
            s += v.x * v.x + v.y * v.y + v.z * v.z + v.w * v.w;
        }
        #pragma unroll
        for (int o = 16; o; o >>= 1) s += __shfl_xor_sync(0xffffffffu, s, o);
        if (lane == 0) g_x2[gwarp] = s;
    }
}

// ---------------------------------------------------------------------------
// Fused GEMM + distance epilogue:
//   out[b][n] = max(x2[b] + w2[n] - 2 * (X @ W)[b][n], 0)
// Classic 128x128 tile, BK=16, 256 threads, 8x8 per-thread micro-tile.
// ---------------------------------------------------------------------------
#define BM 128
#define BN 128
#define BK 16
#define TM 8
#define TN 8

__global__ __launch_bounds__(256, 2)
void gemm_norms_kernel(const float* __restrict__ A,   // [M][K]
                       const float* __restrict__ B,   // [K][N]
                       float* __restrict__ out) {     // [M][N]
    __shared__ float As[BK][BM];   // transposed A tile
    __shared__ float Bs[BK][BN];

    int bx = blockIdx.x;           // N tile index
    int by = blockIdx.y;           // M tile index
    int tid = threadIdx.x;
    int tx = tid & 15;             // 0..15
    int ty = tid >> 4;             // 0..15

    const float* Ab = A + (size_t)by * BM * K_DIM;
    const float* Bb = B + (size_t)bx * BN;

    float acc[TM][TN];
    #pragma unroll
    for (int i = 0; i < TM; i++)
        #pragma unroll
        for (int j = 0; j < TN; j++) acc[i][j] = 0.f;

    for (int k0 = 0; k0 < K_DIM; k0 += BK) {
        // Load A tile (128 x 16) = 512 float4; 2 per thread; store transposed.
        #pragma unroll
        for (int i = 0; i < 2; i++) {
            int l  = tid + i * 256;
            int r  = l >> 2;
            int k4 = l & 3;
            float4 v = *(const float4*)(Ab + (size_t)r * K_DIM + k0 + k4 * 4);
            As[k4 * 4 + 0][r] = v.x;
            As[k4 * 4 + 1][r] = v.y;
            As[k4 * 4 + 2][r] = v.z;
            As[k4 * 4 + 3][r] = v.w;
        }
        // Load B tile (16 x 128) = 512 float4; 2 per thread.
        #pragma unroll
        for (int i = 0; i < 2; i++) {
            int l  = tid + i * 256;
            int kk = l >> 5;
            int n4 = l & 31;
            *(float4*)(&Bs[kk][n4 * 4]) =
                *(const float4*)(Bb + (size_t)(k0 + kk) * N_DIM + n4 * 4);
        }
        __syncthreads();

        #pragma unroll
        for (int kk = 0; kk < BK; kk++) {
            float a[TM], b[TN];
            // vectorized shared loads (aligned: ty*8, tx*8)
            float4 a0 = *(const float4*)(&As[kk][ty * TM]);
            float4 a1 = *(const float4*)(&As[kk][ty * TM + 4]);
            float4 b0 = *(const float4*)(&Bs[kk][tx * TN]);
            float4 b1 = *(const float4*)(&Bs[kk][tx * TN + 4]);
            a[0]=a0.x; a[1]=a0.y; a[2]=a0.z; a[3]=a0.w;
            a[4]=a1.x; a[5]=a1.y; a[6]=a1.z; a[7]=a1.w;
            b[0]=b0.x; b[1]=b0.y; b[2]=b0.z; b[3]=b0.w;
            b[4]=b1.x; b[5]=b1.y; b[6]=b1.z; b[7]=b1.w;
            #pragma unroll
            for (int i = 0; i < TM; i++)
                #pragma unroll
                for (int j = 0; j < TN; j++)
                    acc[i][j] = fmaf(a[i], b[j], acc[i][j]);
        }
        __syncthreads();
    }

    // Epilogue: norms2 = max(x2 + w2 - 2*dot, 0)
    int row0 = by * BM + ty * TM;
    int col0 = bx * BN + tx * TN;
    #pragma unroll
    for (int i = 0; i < TM; i++) {
        float xr = g_x2[row0 + i];
        float4 o0, o1;
        o0.x = fmaxf(xr + g_w2[col0 + 0] - 2.f * acc[i][0], 0.f);
        o0.y = fmaxf(xr + g_w2[col0 + 1] - 2.f * acc[i][1], 0.f);
        o0.z = fmaxf(xr + g_w2[col0 + 2] - 2.f * acc[i][2], 0.f);
        o0.w = fmaxf(xr + g_w2[col0 + 3] - 2.f * acc[i][3], 0.f);
        o1.x = fmaxf(xr + g_w2[col0 + 4] - 2.f * acc[i][4], 0.f);
        o1.y = fmaxf(xr + g_w2[col0 + 5] - 2.f * acc[i][5], 0.f);
        o1.z = fmaxf(xr + g_w2[col0 + 6] - 2.f * acc[i][6], 0.f);
        o1.w = fmaxf(xr + g_w2[col0 + 7] - 2.f * acc[i][7], 0.f);
        float* dst = out + (size_t)(row0 + i) * N_DIM + col0;
        *(float4*)(dst)     = o0;
        *(float4*)(dst + 4) = o1;
    }
}

// ---------------------------------------------------------------------------
// Per-row argmin (first occurrence on ties, matching jnp.argmin)
// ---------------------------------------------------------------------------
__global__ void argmin_kernel(const float* __restrict__ norms) {
    int b = blockIdx.x;
    int t = threadIdx.x;
    const float* row = norms + (size_t)b * N_DIM;

    float best = 3.4e38f;
    int   bi   = N_DIM;
    for (int n = t; n < N_DIM; n += 256) {
        float v = row[n];
        if (v < best) { best = v; bi = n; }   // strided ascending: strict < keeps first idx
    }

    __shared__ float sv[256];
    __shared__ int   si[256];
    sv[t] = best; si[t] = bi;
    __syncthreads();
    #pragma unroll
    for (int s = 128; s > 0; s >>= 1) {
        if (t < s) {
            if (sv[t + s] < sv[t] || (sv[t + s] == sv[t] && si[t + s] < si[t])) {
                sv[t] = sv[t + s];
                si[t] = si[t + s];
            }
        }
        __syncthreads();
    }
    if (t == 0) g_bmu[b] = si[0];
}

// ---------------------------------------------------------------------------
// phi epilogue. Gaussian on 2D grid is separable:
//   phi(n) = er[n/128] * ec[n%128],  sum(phi) = Sr * Sc
// out[b][n] = norms2[b][n] * phi(n) / (Sr*Sc)   (in-place on d_out)
// ---------------------------------------------------------------------------
__global__ void phi_kernel(const float* __restrict__ std_ptr,
                           float* __restrict__ out) {
    int b = blockIdx.x;
    int t = threadIdx.x;   // 256

    __shared__ float er[SIDE], ec[SIDE];
    __shared__ float s_inv;

    int idx = g_bmu[b];
    float r0 = (float)(idx >> 7);
    float c0 = (float)(idx & 127);
    float s  = std_ptr[0];
    float inv2s2 = 0.5f / (s * s);

    if (t < SIDE) {
        float d = (float)t - r0;
        er[t] = expf(-d * d * inv2s2);
    } else if (t < 2 * SIDE) {
        float d = (float)(t - SIDE) - c0;
        ec[t - SIDE] = expf(-d * d * inv2s2);
    }
    __syncthreads();

    if (t == 0) {
        float sr = 0.f, sc = 0.f;
        #pragma unroll 8
        for (int i = 0; i < SIDE; i++) { sr += er[i]; sc += ec[i]; }
        s_inv = 1.0f / (sr * sc);
    }
    __syncthreads();

    float inv = s_inv;
    float4* row = (float4*)(out + (size_t)b * N_DIM);
    for (int n4 = t; n4 < N_DIM / 4; n4 += 256) {
        int n = n4 * 4;
        int r = n >> 7;
        int c = n & 127;
        float e = er[r] * inv;
        float4 v = row[n4];
        v.x *= e * ec[c + 0];
        v.y *= e * ec[c + 1];
        v.z *= e * ec[c + 2];
        v.w *= e * ec[c + 3];
        row[n4] = v;
    }
}

// ---------------------------------------------------------------------------
extern "C" void kernel_launch(void* const* d_in, const int* in_sizes, int n_in,
                              void* d_out, int out_size) {
    const float* x   = (const float*)d_in[0];   // (2048, 512)
    const float* w   = (const float*)d_in[1];   // (512, 16384)
    const float* std = (const float*)d_in[2];   // scalar
    float* out = (float*)d_out;                 // (2048, 16384)

    // 1) column norms of W
    w2_kernel<<<(N_DIM + 255) / 256, 256>>>(w);
    // 2) row norms of X
    x2_kernel<<<(M_DIM * 32 + 255) / 256, 256>>>(x);
    // 3) fused GEMM + squared-distance epilogue -> d_out holds norms2
    dim3 grid(N_DIM / BN, M_DIM / BM);
    gemm_norms_kernel<<<grid, 256>>>(x, w, out);
    // 4) per-row BMU
    argmin_kernel<<<M_DIM, 256>>>(out);
    // 5) gaussian phi (separable normalization) applied in-place
    phi_kernel<<<M_DIM, 256>>>(std, out);
}

// round 3
// speedup vs baseline: 2.5369x; 2.5369x over previous
#include <cuda_runtime.h>
#include <cuda_bf16.h>
#include <math.h>
#include <float.h>
#include <stdint.h>

// Problem dims (fixed by the dataset)
#define M_DIM 2048      // batch B
#define K_DIM 512       // input size D
#define N_DIM 16384     // output size (side*side)
#define SIDE  128
#define NTILES (N_DIM/128)   // 128 column tiles
#define KTOT  1024           // logical K: [xh | xl]

// ---------------------------------------------------------------------------
// Scratch (no cudaMalloc allowed)
// ---------------------------------------------------------------------------
__device__ __align__(128) __nv_bfloat16 g_ax[M_DIM * KTOT];   // A: [xh | xl] per row
__device__ __align__(128) __nv_bfloat16 g_bw[N_DIM * K_DIM];  // B: W^T hi [N][K]
__device__ float g_w2[N_DIM];
__device__ float g_x2[M_DIM];
__device__ int   g_bmu[M_DIM];
__device__ unsigned long long g_key[M_DIM * NTILES];  // per (row, tile) (min<<32|idx)

__device__ __forceinline__ uint32_t smem_u32(const void* p) {
    uint32_t a;
    asm("{ .reg .u64 t; cvta.to.shared.u64 t, %1; cvt.u32.u64 %0, t; }" : "=r"(a) : "l"(p));
    return a;
}

__device__ __forceinline__ void cp16(uint32_t dst, const void* src) {
    asm volatile("cp.async.cg.shared.global [%0], [%1], 16;" :: "r"(dst), "l"(src));
}
__device__ __forceinline__ void cp_commit() { asm volatile("cp.async.commit_group;"); }
template <int N> __device__ __forceinline__ void cp_wait() {
    asm volatile("cp.async.wait_group %0;" :: "n"(N));
}

__device__ __forceinline__ void ldm4(uint32_t& r0, uint32_t& r1, uint32_t& r2, uint32_t& r3,
                                     uint32_t addr) {
    asm volatile("ldmatrix.sync.aligned.m8n8.x4.shared.b16 {%0,%1,%2,%3}, [%4];"
                 : "=r"(r0), "=r"(r1), "=r"(r2), "=r"(r3) : "r"(addr));
}

__device__ __forceinline__ void mma16816(float* c, uint32_t a0, uint32_t a1, uint32_t a2,
                                         uint32_t a3, uint32_t b0, uint32_t b1) {
    asm volatile(
        "mma.sync.aligned.m16n8k16.row.col.f32.bf16.bf16.f32 "
        "{%0,%1,%2,%3}, {%4,%5,%6,%7}, {%8,%9}, {%0,%1,%2,%3};"
        : "+f"(c[0]), "+f"(c[1]), "+f"(c[2]), "+f"(c[3])
        : "r"(a0), "r"(a1), "r"(a2), "r"(a3), "r"(b0), "r"(b1));
}

// ---------------------------------------------------------------------------
// prep_x: fp32 x -> bf16 hi (cols 0..511) + lo (cols 512..1023); exact x2
// ---------------------------------------------------------------------------
__global__ void prep_x_kernel(const float* __restrict__ x) {
    int row = blockIdx.x, t = threadIdx.x;  // 128 threads
    float4 v = ((const float4*)(x + (size_t)row * K_DIM))[t];
    __nv_bfloat162 h01 = __floats2bfloat162_rn(v.x, v.y);
    __nv_bfloat162 h23 = __floats2bfloat162_rn(v.z, v.w);
    float2 f01 = __bfloat1622float2(h01);
    float2 f23 = __bfloat1622float2(h23);
    __nv_bfloat162 l01 = __floats2bfloat162_rn(v.x - f01.x, v.y - f01.y);
    __nv_bfloat162 l23 = __floats2bfloat162_rn(v.z - f23.x, v.w - f23.y);
    __nv_bfloat162* a2 = (__nv_bfloat162*)(g_ax + (size_t)row * KTOT);
    a2[2 * t]           = h01;  a2[2 * t + 1]           = h23;
    a2[256 + 2 * t]     = l01;  a2[256 + 2 * t + 1]     = l23;

    float s = v.x * v.x + v.y * v.y + v.z * v.z + v.w * v.w;
    #pragma unroll
    for (int o = 16; o; o >>= 1) s += __shfl_xor_sync(0xffffffffu, s, o);
    __shared__ float ws[4];
    if ((t & 31) == 0) ws[t >> 5] = s;
    __syncthreads();
    if (t == 0) g_x2[row] = ws[0] + ws[1] + ws[2] + ws[3];
}

// ---------------------------------------------------------------------------
// prep_w: transpose W [K][N] -> W^T [N][K] bf16 hi
// ---------------------------------------------------------------------------
__global__ void prep_w_kernel(const float* __restrict__ W) {
    __shared__ float T[32][33];
    int n0 = blockIdx.x * 32, k0 = blockIdx.y * 32;
    int tx = threadIdx.x, ty = threadIdx.y;  // 32 x 8
    #pragma unroll
    for (int i = 0; i < 4; i++)
        T[ty + 8 * i][tx] = W[(size_t)(k0 + ty + 8 * i) * N_DIM + n0 + tx];
    __syncthreads();
    #pragma unroll
    for (int i = 0; i < 4; i++) {
        int n = n0 + ty + 8 * i;
        int kk = k0 + tx;
        g_bw[(size_t)n * K_DIM + kk] = __float2bfloat16(T[tx][ty + 8 * i]);
    }
}

// ---------------------------------------------------------------------------
// w2[n] = sum_k W[k][n]^2 (fp32 exact)
// ---------------------------------------------------------------------------
__global__ void w2_kernel(const float* __restrict__ W) {
    int n = blockIdx.x * blockDim.x + threadIdx.x;
    if (n < N_DIM) {
        float s = 0.f;
        #pragma unroll 8
        for (int k = 0; k < K_DIM; k++) {
            float v = W[(size_t)k * N_DIM + n];
            s += v * v;
        }
        g_w2[n] = s;
    }
}

// ---------------------------------------------------------------------------
// HMMA GEMM: CTA 128x128, 8 warps (warp 32x64), K=1024 (hi|lo), BK=64,
// 3-stage cp.async pipeline. Epilogue: norms2 + per-(row,tile) argmin key.
// ---------------------------------------------------------------------------
#define NCHUNK 16
#define STAGE_BYTES 32768                 // A 16KB + B 16KB
#define SMEM_KEY   (3 * STAGE_BYTES)      // 98304
#define SMEM_W2    (SMEM_KEY + 1024)
#define SMEM_DYN   (SMEM_W2 + 512)

__device__ __forceinline__ void load_stage(uint32_t sm, int stage, int kc, int m0, int n0, int tid) {
    uint32_t A = sm + stage * STAGE_BYTES;
    uint32_t B = A + 16384;
    const __nv_bfloat16* ag = g_ax + (size_t)m0 * KTOT + kc * 64;
    const __nv_bfloat16* bg = g_bw + (size_t)n0 * K_DIM + (kc & 7) * 64;
    #pragma unroll
    for (int i = 0; i < 4; i++) {
        int lin = tid + 256 * i;
        int row = lin >> 3;
        int c = lin & 7;
        int sw = (c ^ (row & 7)) << 4;
        cp16(A + row * 128 + sw, ag + (size_t)row * KTOT + c * 8);
        cp16(B + row * 128 + sw, bg + (size_t)row * K_DIM + c * 8);
    }
}

__global__ void __launch_bounds__(256, 1) gemm_kernel(float* __restrict__ out) {
    extern __shared__ char smem[];
    uint32_t sm = smem_u32(smem);
    unsigned long long* skey = (unsigned long long*)(smem + SMEM_KEY);
    float* w2s = (float*)(smem + SMEM_W2);

    int tid = threadIdx.x, wid = tid >> 5, lane = tid & 31;
    int n0 = blockIdx.x * 128, m0 = blockIdx.y * 128;
    int wm = wid >> 1, wn = wid & 1;

    if (tid < 128) {
        skey[tid] = ~0ull;
        w2s[tid] = g_w2[n0 + tid];
    }

    float c[2][8][4];
    #pragma unroll
    for (int i = 0; i < 2; i++)
        #pragma unroll
        for (int j = 0; j < 8; j++)
            #pragma unroll
            for (int q = 0; q < 4; q++) c[i][j][q] = 0.f;

    // Per-lane ldmatrix address components
    int rowA = wm * 32 + (lane & 15);          // + f*16
    int chA  = lane >> 4;                      // k-chunk sub
    int rowB = wn * 64 + (lane & 7) + ((lane >> 4) << 3);  // + g*16
    int chB  = (lane >> 3) & 1;

    load_stage(sm, 0, 0, m0, n0, tid); cp_commit();
    load_stage(sm, 1, 1, m0, n0, tid); cp_commit();

    #pragma unroll 1
    for (int kc = 0; kc < NCHUNK; kc++) {
        if (kc + 2 < NCHUNK) {
            cp_wait<1>();
            __syncthreads();
            load_stage(sm, (kc + 2) % 3, kc + 2, m0, n0, tid);
            cp_commit();
        } else {
            cp_wait<0>();
            __syncthreads();
        }
        uint32_t A = sm + (kc % 3) * STAGE_BYTES;
        uint32_t B = A + 16384;

        #pragma unroll
        for (int s = 0; s < 4; s++) {
            uint32_t af[2][4], bf[4][4];
            #pragma unroll
            for (int f = 0; f < 2; f++) {
                int r = rowA + f * 16;
                int ch = 2 * s + chA;
                ldm4(af[f][0], af[f][1], af[f][2], af[f][3],
                     A + r * 128 + (((ch) ^ (r & 7)) << 4));
            }
            #pragma unroll
            for (int g = 0; g < 4; g++) {
                int r = rowB + g * 16;
                int ch = 2 * s + chB;
                ldm4(bf[g][0], bf[g][1], bf[g][2], bf[g][3],
                     B + r * 128 + (((ch) ^ (r & 7)) << 4));
            }
            #pragma unroll
            for (int f = 0; f < 2; f++)
                #pragma unroll
                for (int g = 0; g < 4; g++) {
                    mma16816(c[f][g * 2 + 0], af[f][0], af[f][1], af[f][2], af[f][3],
                             bf[g][0], bf[g][1]);
                    mma16816(c[f][g * 2 + 1], af[f][0], af[f][1], af[f][2], af[f][3],
                             bf[g][2], bf[g][3]);
                }
        }
        __syncthreads();
    }

    // ---- epilogue: norms2 + per-row min over this CTA's 128 cols ----
    int lr = lane >> 2, lc = lane & 3;
    #pragma unroll
    for (int mi = 0; mi < 2; mi++) {
        #pragma unroll
        for (int half = 0; half < 2; half++) {
            int rowl = wm * 32 + mi * 16 + half * 8 + lr;
            int r = m0 + rowl;
            float x2v = g_x2[r];
            float best = FLT_MAX;
            int bestc = 0;
            float2 vals[8];
            #pragma unroll
            for (int ni = 0; ni < 8; ni++) {
                int cl = wn * 64 + ni * 8 + 2 * lc;
                float v0 = fmaxf(x2v + w2s[cl] - 2.f * c[mi][ni][half * 2 + 0], 0.f);
                float v1 = fmaxf(x2v + w2s[cl + 1] - 2.f * c[mi][ni][half * 2 + 1], 0.f);
                vals[ni] = make_float2(v0, v1);
                if (v0 < best) { best = v0; bestc = cl; }
                if (v1 < best) { best = v1; bestc = cl + 1; }
            }
            float* orow = out + (size_t)r * N_DIM + n0;
            #pragma unroll
            for (int ni = 0; ni < 8; ni++)
                *(float2*)(orow + wn * 64 + ni * 8 + 2 * lc) = vals[ni];
            #pragma unroll
            for (int off = 1; off <= 2; off <<= 1) {
                float ob = __shfl_xor_sync(0xffffffffu, best, off);
                int oc = __shfl_xor_sync(0xffffffffu, bestc, off);
                if (ob < best || (ob == best && oc < bestc)) { best = ob; bestc = oc; }
            }
            if (lc == 0)
                atomicMin(&skey[rowl],
                          ((unsigned long long)__float_as_uint(best) << 32) |
                          (unsigned)(n0 + bestc));
        }
    }
    __syncthreads();
    if (tid < 128)
        g_key[(size_t)(m0 + tid) * NTILES + blockIdx.x] = skey[tid];
}

// ---------------------------------------------------------------------------
// Argmin repair: reduce per-tile keys; recompute exact fp32 distance for all
// candidates within min+2.0; pick exact argmin (tie -> lowest index).
// ---------------------------------------------------------------------------
__global__ void repair_kernel(const float* __restrict__ x,
                              const float* __restrict__ W,
                              const float* __restrict__ out) {
    int b = blockIdx.x, t = threadIdx.x;  // 128 threads
    __shared__ float xrow[K_DIM];
    __shared__ unsigned long long skey[128];
    __shared__ float sred[128];
    __shared__ int cand[64];
    __shared__ int ncand;
    __shared__ unsigned long long sbest;

    ((float4*)xrow)[t] = ((const float4*)(x + (size_t)b * K_DIM))[t];
    unsigned long long mykey = g_key[(size_t)b * NTILES + t];
    skey[t] = mykey;
    if (t == 0) { ncand = 0; sbest = 0xFFFFFFFFFFFFFFFFull; }
    __syncthreads();
    #pragma unroll
    for (int s = 64; s > 0; s >>= 1) {
        if (t < s) skey[t] = (skey[t + s] < skey[t]) ? skey[t + s] : skey[t];
        __syncthreads();
    }
    float thr = __uint_as_float((unsigned)(skey[0] >> 32)) + 2.0f;
    float tmin = __uint_as_float((unsigned)(mykey >> 32));
    if (tmin < thr) {
        const float* row = out + (size_t)b * N_DIM + t * 128;
        for (int cidx = 0; cidx < 128; cidx++) {
            if (row[cidx] < thr) {
                int i = atomicAdd(&ncand, 1);
                if (i < 64) cand[i] = t * 128 + cidx;
            }
        }
    }
    __syncthreads();
    int nc = min(ncand, 64);
    float x2b = g_x2[b];
    for (int i = 0; i < nc; i++) {
        int n = cand[i];
        float p = 0.f;
        #pragma unroll
        for (int kk = 0; kk < 4; kk++) {
            int kidx = t + kk * 128;
            p = fmaf(xrow[kidx], W[(size_t)kidx * N_DIM + n], p);
        }
        sred[t] = p;
        __syncthreads();
        #pragma unroll
        for (int s = 64; s > 0; s >>= 1) {
            if (t < s) sred[t] += sred[t + s];
            __syncthreads();
        }
        if (t == 0) {
            float ex = fmaxf(x2b + g_w2[n] - 2.0f * sred[0], 0.0f);
            unsigned long long key =
                ((unsigned long long)__float_as_uint(ex) << 32) | (unsigned)n;
            if (key < sbest) sbest = key;
        }
        __syncthreads();
    }
    if (t == 0) g_bmu[b] = (int)(sbest & 0xFFFFFFFFu);
}

// ---------------------------------------------------------------------------
// phi: separable Gaussian around BMU, normalized; in-place on d_out
// ---------------------------------------------------------------------------
__global__ void phi_kernel(const float* __restrict__ std_ptr,
                           float* __restrict__ out) {
    int b = blockIdx.x;
    int t = threadIdx.x;  // 256
    __shared__ float er[SIDE], ec[SIDE];
    __shared__ float s_inv;

    int idx = g_bmu[b];
    float r0 = (float)(idx >> 7);
    float c0 = (float)(idx & 127);
    float s = std_ptr[0];
    float inv2s2 = 0.5f / (s * s);

    if (t < SIDE) {
        float d = (float)t - r0;
        er[t] = expf(-d * d * inv2s2);
    } else if (t < 2 * SIDE) {
        float d = (float)(t - SIDE) - c0;
        ec[t - SIDE] = expf(-d * d * inv2s2);
    }
    __syncthreads();
    if (t == 0) {
        float sr = 0.f, sc = 0.f;
        #pragma unroll 8
        for (int i = 0; i < SIDE; i++) { sr += er[i]; sc += ec[i]; }
        s_inv = 1.0f / (sr * sc);
    }
    __syncthreads();

    float inv = s_inv;
    float4* row = (float4*)(out + (size_t)b * N_DIM);
    for (int n4 = t; n4 < N_DIM / 4; n4 += 256) {
        int n = n4 * 4;
        int r = n >> 7;
        int c = n & 127;
        float e = er[r] * inv;
        float4 v = row[n4];
        v.x *= e * ec[c + 0];
        v.y *= e * ec[c + 1];
        v.z *= e * ec[c + 2];
        v.w *= e * ec[c + 3];
        row[n4] = v;
    }
}

// ---------------------------------------------------------------------------
extern "C" void kernel_launch(void* const* d_in, const int* in_sizes, int n_in,
                              void* d_out, int out_size) {
    const float* x    = (const float*)d_in[0];   // (2048, 512)
    const float* w    = (const float*)d_in[1];   // (512, 16384)
    const float* stdp = (const float*)d_in[2];   // scalar
    float* out = (float*)d_out;                  // (2048, 16384)

    cudaFuncSetAttribute(gemm_kernel, cudaFuncAttributeMaxDynamicSharedMemorySize, SMEM_DYN);

    // 1) prep: bf16 hi/lo split of x, W^T hi, exact norms
    prep_x_kernel<<<M_DIM, 128>>>(x);
    prep_w_kernel<<<dim3(N_DIM / 32, K_DIM / 32), dim3(32, 8)>>>(w);
    w2_kernel<<<N_DIM / 256, 256>>>(w);
    // 2) HMMA GEMM + norms2 epilogue + per-tile argmin keys
    gemm_kernel<<<dim3(N_DIM / 128, M_DIM / 128), 256, SMEM_DYN>>>(out);
    // 3) exact argmin repair -> g_bmu
    repair_kernel<<<M_DIM, 128>>>(x, w, out);
    // 4) gaussian phi (separable), in-place
    phi_kernel<<<M_DIM, 256>>>(stdp, out);
}

// round 4
// speedup vs baseline: 4.1088x; 1.6196x over previous
#include <cuda_runtime.h>
#include <cuda_fp16.h>
#include <math.h>
#include <float.h>
#include <stdint.h>

// Problem dims (fixed by the dataset)
#define M_DIM 2048      // batch B
#define K_DIM 512       // input size D
#define N_DIM 16384     // output size (side*side)
#define SIDE  128
#define NTILES (N_DIM/128)   // 128 column tiles
#define W2PARTS 16           // K_DIM/32 partial sums

// ---------------------------------------------------------------------------
// Scratch (no cudaMalloc allowed)
// ---------------------------------------------------------------------------
__device__ __align__(128) __half g_ax[M_DIM * K_DIM];   // A: fp16(x)  [M][K]
__device__ __align__(128) __half g_bw[N_DIM * K_DIM];   // B: fp16(W^T) [N][K]
__device__ float g_w2p[W2PARTS][N_DIM];
__device__ float g_w2[N_DIM];
__device__ float g_x2[M_DIM];
__device__ int   g_bmu[M_DIM];
__device__ unsigned long long g_key[M_DIM * NTILES];  // per (row, tile) (min<<32|idx)

__device__ __forceinline__ uint32_t smem_u32(const void* p) {
    uint32_t a;
    asm("{ .reg .u64 t; cvta.to.shared.u64 t, %1; cvt.u32.u64 %0, t; }" : "=r"(a) : "l"(p));
    return a;
}

__device__ __forceinline__ void cp16(uint32_t dst, const void* src) {
    asm volatile("cp.async.cg.shared.global [%0], [%1], 16;" :: "r"(dst), "l"(src));
}
__device__ __forceinline__ void cp_commit() { asm volatile("cp.async.commit_group;"); }
template <int N> __device__ __forceinline__ void cp_wait() {
    asm volatile("cp.async.wait_group %0;" :: "n"(N));
}

__device__ __forceinline__ void ldm4(uint32_t& r0, uint32_t& r1, uint32_t& r2, uint32_t& r3,
                                     uint32_t addr) {
    asm volatile("ldmatrix.sync.aligned.m8n8.x4.shared.b16 {%0,%1,%2,%3}, [%4];"
                 : "=r"(r0), "=r"(r1), "=r"(r2), "=r"(r3) : "r"(addr));
}

__device__ __forceinline__ void mma16816(float* c, uint32_t a0, uint32_t a1, uint32_t a2,
                                         uint32_t a3, uint32_t b0, uint32_t b1) {
    asm volatile(
        "mma.sync.aligned.m16n8k16.row.col.f32.f16.f16.f32 "
        "{%0,%1,%2,%3}, {%4,%5,%6,%7}, {%8,%9}, {%0,%1,%2,%3};"
        : "+f"(c[0]), "+f"(c[1]), "+f"(c[2]), "+f"(c[3])
        : "r"(a0), "r"(a1), "r"(a2), "r"(a3), "r"(b0), "r"(b1));
}

// ---------------------------------------------------------------------------
// prep_x: fp32 x -> fp16; exact x2
// ---------------------------------------------------------------------------
__global__ void prep_x_kernel(const float* __restrict__ x) {
    int row = blockIdx.x, t = threadIdx.x;  // 128 threads
    float4 v = ((const float4*)(x + (size_t)row * K_DIM))[t];
    __half2* a2 = (__half2*)(g_ax + (size_t)row * K_DIM);
    a2[2 * t]     = __floats2half2_rn(v.x, v.y);
    a2[2 * t + 1] = __floats2half2_rn(v.z, v.w);

    float s = v.x * v.x + v.y * v.y + v.z * v.z + v.w * v.w;
    #pragma unroll
    for (int o = 16; o; o >>= 1) s += __shfl_xor_sync(0xffffffffu, s, o);
    __shared__ float ws[4];
    if ((t & 31) == 0) ws[t >> 5] = s;
    __syncthreads();
    if (t == 0) g_x2[row] = ws[0] + ws[1] + ws[2] + ws[3];
}

// ---------------------------------------------------------------------------
// prep_w: transpose W [K][N] -> W^T [N][K] fp16 + per-(32k)-block w2 partials
// ---------------------------------------------------------------------------
__global__ void prep_w_kernel(const float* __restrict__ W) {
    __shared__ float T[32][33];
    int n0 = blockIdx.x * 32, k0 = blockIdx.y * 32;
    int tx = threadIdx.x, ty = threadIdx.y;  // 32 x 8
    #pragma unroll
    for (int i = 0; i < 4; i++)
        T[ty + 8 * i][tx] = W[(size_t)(k0 + ty + 8 * i) * N_DIM + n0 + tx];
    __syncthreads();
    #pragma unroll
    for (int i = 0; i < 4; i++) {
        int n = n0 + ty + 8 * i;
        float v = T[tx][ty + 8 * i];      // element (k0+tx, n)
        g_bw[(size_t)n * K_DIM + k0 + tx] = __float2half(v);
        float s = v * v;                  // reduce over tx (k within block)
        #pragma unroll
        for (int o = 16; o; o >>= 1) s += __shfl_xor_sync(0xffffffffu, s, o);
        if (tx == 0) g_w2p[blockIdx.y][n] = s;
    }
}

__global__ void w2sum_kernel() {
    int n = blockIdx.x * blockDim.x + threadIdx.x;
    float s = 0.f;
    #pragma unroll
    for (int p = 0; p < W2PARTS; p++) s += g_w2p[p][n];
    g_w2[n] = s;
}

// ---------------------------------------------------------------------------
// HMMA GEMM: CTA 256x128, 8 warps (warp 64x64), K=512 fp16, BK=64,
// 3-stage cp.async pipeline. Epilogue: norms2 + per-(row,tile) argmin key.
// ---------------------------------------------------------------------------
#define NCHUNK 8
#define A_BYTES 32768                      // 256 rows x 128B
#define B_BYTES 16384                      // 128 rows x 128B
#define STAGE_BYTES (A_BYTES + B_BYTES)    // 49152
#define SMEM_KEY   (3 * STAGE_BYTES)       // 147456
#define SMEM_W2    (SMEM_KEY + 2048)
#define SMEM_DYN   (SMEM_W2 + 512)

__device__ __forceinline__ void load_stage(uint32_t sm, int stage, int kc, int m0, int n0, int tid) {
    uint32_t A = sm + stage * STAGE_BYTES;
    uint32_t B = A + A_BYTES;
    const __half* ag = g_ax + (size_t)m0 * K_DIM + kc * 64;
    const __half* bg = g_bw + (size_t)n0 * K_DIM + kc * 64;
    #pragma unroll
    for (int i = 0; i < 8; i++) {          // A: 2048 16B chunks
        int lin = tid + 256 * i;
        int row = lin >> 3;
        int c = lin & 7;
        int sw = (c ^ (row & 7)) << 4;
        cp16(A + row * 128 + sw, ag + (size_t)row * K_DIM + c * 8);
    }
    #pragma unroll
    for (int i = 0; i < 4; i++) {          // B: 1024 16B chunks
        int lin = tid + 256 * i;
        int row = lin >> 3;
        int c = lin & 7;
        int sw = (c ^ (row & 7)) << 4;
        cp16(B + row * 128 + sw, bg + (size_t)row * K_DIM + c * 8);
    }
}

__global__ void __launch_bounds__(256, 1) gemm_kernel(float* __restrict__ out) {
    extern __shared__ char smem[];
    uint32_t sm = smem_u32(smem);
    unsigned long long* skey = (unsigned long long*)(smem + SMEM_KEY);
    float* w2s = (float*)(smem + SMEM_W2);

    int tid = threadIdx.x, wid = tid >> 5, lane = tid & 31;
    int n0 = blockIdx.x * 128, m0 = blockIdx.y * 256;
    int wm = wid >> 1, wn = wid & 1;       // 4 x 2 warps; warp tile 64x64

    skey[tid] = ~0ull;
    if (tid < 128) w2s[tid] = g_w2[n0 + tid];

    float c[4][8][4];
    #pragma unroll
    for (int i = 0; i < 4; i++)
        #pragma unroll
        for (int j = 0; j < 8; j++)
            #pragma unroll
            for (int q = 0; q < 4; q++) c[i][j][q] = 0.f;

    // Per-lane ldmatrix address components
    int rowA = wm * 64 + (lane & 15);                      // + f*16
    int chA  = lane >> 4;
    int rowB = wn * 64 + (lane & 7) + ((lane >> 4) << 3);  // + g*16
    int chB  = (lane >> 3) & 1;

    load_stage(sm, 0, 0, m0, n0, tid); cp_commit();
    load_stage(sm, 1, 1, m0, n0, tid); cp_commit();

    #pragma unroll 1
    for (int kc = 0; kc < NCHUNK; kc++) {
        if (kc + 2 < NCHUNK) {
            cp_wait<1>();
            __syncthreads();
            load_stage(sm, (kc + 2) % 3, kc + 2, m0, n0, tid);
            cp_commit();
        } else {
            cp_wait<0>();
            __syncthreads();
        }
        uint32_t A = sm + (kc % 3) * STAGE_BYTES;
        uint32_t B = A + A_BYTES;

        #pragma unroll
        for (int s = 0; s < 4; s++) {
            uint32_t af[4][4], bf[4][4];
            #pragma unroll
            for (int f = 0; f < 4; f++) {
                int r = rowA + f * 16;
                int ch = 2 * s + chA;
                ldm4(af[f][0], af[f][1], af[f][2], af[f][3],
                     A + r * 128 + ((ch ^ (r & 7)) << 4));
            }
            #pragma unroll
            for (int g = 0; g < 4; g++) {
                int r = rowB + g * 16;
                int ch = 2 * s + chB;
                ldm4(bf[g][0], bf[g][1], bf[g][2], bf[g][3],
                     B + r * 128 + ((ch ^ (r & 7)) << 4));
            }
            #pragma unroll
            for (int f = 0; f < 4; f++)
                #pragma unroll
                for (int g = 0; g < 4; g++) {
                    mma16816(c[f][g * 2 + 0], af[f][0], af[f][1], af[f][2], af[f][3],
                             bf[g][0], bf[g][1]);
                    mma16816(c[f][g * 2 + 1], af[f][0], af[f][1], af[f][2], af[f][3],
                             bf[g][2], bf[g][3]);
                }
        }
        __syncthreads();
    }

    // ---- epilogue: norms2 + per-row min over this CTA's 128 cols ----
    int lr = lane >> 2, lc = lane & 3;
    #pragma unroll
    for (int mi = 0; mi < 4; mi++) {
        #pragma unroll
        for (int half = 0; half < 2; half++) {
            int rowl = wm * 64 + mi * 16 + half * 8 + lr;
            int r = m0 + rowl;
            float x2v = g_x2[r];
            float best = FLT_MAX;
            int bestc = 0;
            float2 vals[8];
            #pragma unroll
            for (int ni = 0; ni < 8; ni++) {
                int cl = wn * 64 + ni * 8 + 2 * lc;
                float v0 = fmaxf(x2v + w2s[cl] - 2.f * c[mi][ni][half * 2 + 0], 0.f);
                float v1 = fmaxf(x2v + w2s[cl + 1] - 2.f * c[mi][ni][half * 2 + 1], 0.f);
                vals[ni] = make_float2(v0, v1);
                if (v0 < best) { best = v0; bestc = cl; }
                if (v1 < best) { best = v1; bestc = cl + 1; }
            }
            float* orow = out + (size_t)r * N_DIM + n0;
            #pragma unroll
            for (int ni = 0; ni < 8; ni++)
                *(float2*)(orow + wn * 64 + ni * 8 + 2 * lc) = vals[ni];
            #pragma unroll
            for (int off = 1; off <= 2; off <<= 1) {
                float ob = __shfl_xor_sync(0xffffffffu, best, off);
                int oc = __shfl_xor_sync(0xffffffffu, bestc, off);
                if (ob < best || (ob == best && oc < bestc)) { best = ob; bestc = oc; }
            }
            if (lc == 0)
                atomicMin(&skey[rowl],
                          ((unsigned long long)__float_as_uint(best) << 32) |
                          (unsigned)(n0 + bestc));
        }
    }
    __syncthreads();
    g_key[(size_t)(m0 + tid) * NTILES + blockIdx.x] = skey[tid];
}

// ---------------------------------------------------------------------------
// Argmin repair: reduce per-tile keys; recompute exact fp32 distance for all
// candidates within min+2.0; pick exact argmin (tie -> lowest index).
// ---------------------------------------------------------------------------
__global__ void repair_kernel(const float* __restrict__ x,
                              const float* __restrict__ W,
                              const float* __restrict__ out) {
    int b = blockIdx.x, t = threadIdx.x;  // 128 threads
    __shared__ float xrow[K_DIM];
    __shared__ unsigned long long skey[128];
    __shared__ float sred[128];
    __shared__ int cand[64];
    __shared__ int ncand;
    __shared__ unsigned long long sbest;

    ((float4*)xrow)[t] = ((const float4*)(x + (size_t)b * K_DIM))[t];
    unsigned long long mykey = g_key[(size_t)b * NTILES + t];
    skey[t] = mykey;
    if (t == 0) { ncand = 0; sbest = 0xFFFFFFFFFFFFFFFFull; }
    __syncthreads();
    #pragma unroll
    for (int s = 64; s > 0; s >>= 1) {
        if (t < s) skey[t] = (skey[t + s] < skey[t]) ? skey[t + s] : skey[t];
        __syncthreads();
    }
    float thr = __uint_as_float((unsigned)(skey[0] >> 32)) + 2.0f;
    float tmin = __uint_as_float((unsigned)(mykey >> 32));
    if (tmin < thr) {
        const float* row = out + (size_t)b * N_DIM + t * 128;
        for (int cidx = 0; cidx < 128; cidx++) {
            if (row[cidx] < thr) {
                int i = atomicAdd(&ncand, 1);
                if (i < 64) cand[i] = t * 128 + cidx;
            }
        }
    }
    __syncthreads();
    int nc = min(ncand, 64);
    float x2b = g_x2[b];
    for (int i = 0; i < nc; i++) {
        int n = cand[i];
        float p = 0.f;
        #pragma unroll
        for (int kk = 0; kk < 4; kk++) {
            int kidx = t + kk * 128;
            p = fmaf(xrow[kidx], W[(size_t)kidx * N_DIM + n], p);
        }
        sred[t] = p;
        __syncthreads();
        #pragma unroll
        for (int s = 64; s > 0; s >>= 1) {
            if (t < s) sred[t] += sred[t + s];
            __syncthreads();
        }
        if (t == 0) {
            float ex = fmaxf(x2b + g_w2[n] - 2.0f * sred[0], 0.0f);
            unsigned long long key =
                ((unsigned long long)__float_as_uint(ex) << 32) | (unsigned)n;
            if (key < sbest) sbest = key;
        }
        __syncthreads();
    }
    if (t == 0) g_bmu[b] = (int)(sbest & 0xFFFFFFFFu);
}

// ---------------------------------------------------------------------------
// phi: separable Gaussian around BMU, normalized; in-place on d_out
// ---------------------------------------------------------------------------
__global__ void phi_kernel(const float* __restrict__ std_ptr,
                           float* __restrict__ out) {
    int b = blockIdx.x;
    int t = threadIdx.x;  // 256
    __shared__ float er[SIDE], ec[SIDE];
    __shared__ float s_inv;

    int idx = g_bmu[b];
    float r0 = (float)(idx >> 7);
    float c0 = (float)(idx & 127);
    float s = std_ptr[0];
    float inv2s2 = 0.5f / (s * s);

    if (t < SIDE) {
        float d = (float)t - r0;
        er[t] = expf(-d * d * inv2s2);
    } else if (t < 2 * SIDE) {
        float d = (float)(t - SIDE) - c0;
        ec[t - SIDE] = expf(-d * d * inv2s2);
    }
    __syncthreads();
    if (t == 0) {
        float sr = 0.f, sc = 0.f;
        #pragma unroll 8
        for (int i = 0; i < SIDE; i++) { sr += er[i]; sc += ec[i]; }
        s_inv = 1.0f / (sr * sc);
    }
    __syncthreads();

    float inv = s_inv;
    float4* row = (float4*)(out + (size_t)b * N_DIM);
    for (int n4 = t; n4 < N_DIM / 4; n4 += 256) {
        int n = n4 * 4;
        int r = n >> 7;
        int c = n & 127;
        float e = er[r] * inv;
        float4 v = row[n4];
        v.x *= e * ec[c + 0];
        v.y *= e * ec[c + 1];
        v.z *= e * ec[c + 2];
        v.w *= e * ec[c + 3];
        row[n4] = v;
    }
}

// ---------------------------------------------------------------------------
extern "C" void kernel_launch(void* const* d_in, const int* in_sizes, int n_in,
                              void* d_out, int out_size) {
    const float* x    = (const float*)d_in[0];   // (2048, 512)
    const float* w    = (const float*)d_in[1];   // (512, 16384)
    const float* stdp = (const float*)d_in[2];   // scalar
    float* out = (float*)d_out;                  // (2048, 16384)

    cudaFuncSetAttribute(gemm_kernel, cudaFuncAttributeMaxDynamicSharedMemorySize, SMEM_DYN);

    // 1) prep: fp16 x, fp16 W^T + w2 partials, exact norms
    prep_x_kernel<<<M_DIM, 128>>>(x);
    prep_w_kernel<<<dim3(N_DIM / 32, K_DIM / 32), dim3(32, 8)>>>(w);
    w2sum_kernel<<<N_DIM / 256, 256>>>();
    // 2) HMMA fp16 GEMM + norms2 epilogue + per-tile argmin keys
    gemm_kernel<<<dim3(N_DIM / 128, M_DIM / 256), 256, SMEM_DYN>>>(out);
    // 3) exact argmin repair -> g_bmu
    repair_kernel<<<M_DIM, 128>>>(x, w, out);
    // 4) gaussian phi (separable), in-place
    phi_kernel<<<M_DIM, 256>>>(stdp, out);
}